// round 12
// baseline (speedup 1.0000x reference)
#include <cuda_runtime.h>

#define NTHREADS 256
#define SAMPLES  32
#define HDIM     50
#define G4       256            // 64 units * 4 gates, cols 4j+g
#define TSTEPS   256
#define HW       12             // floats per unit row in warp h region (48B)
#define HBW      (64*HW)        // 768 floats per buffer per warp
#define XROW     68             // x tile row: 32 samples dup (64) + 4 pad
#define XBUF     (32*XROW)

typedef unsigned long long ull;

__device__ __forceinline__ ull pack2(float lo, float hi) {
    ull r; asm("mov.b64 %0, {%1,%2};" : "=l"(r) : "f"(lo), "f"(hi)); return r;
}
__device__ __forceinline__ void unpack2(ull v, float& lo, float& hi) {
    asm("mov.b64 {%0,%1}, %2;" : "=f"(lo), "=f"(hi) : "l"(v));
}
__device__ __forceinline__ ull fma2(ull a, ull b, ull c) {
    ull d; asm("fma.rn.f32x2 %0, %1, %2, %3;" : "=l"(d) : "l"(a), "l"(b), "l"(c)); return d;
}
__device__ __forceinline__ float sigmoidf_(float x) {
    return __fdividef(1.f, 1.f + __expf(-x));
}
__device__ __forceinline__ float tanhf_(float x) {
    return fmaf(2.f, sigmoidf_(2.f * x), -1.f);
}

// Dynamic shared layout (floats):
//  Ws  [51*256]   : rows 0..49 = W_hh (col 4j+g), row 50 = W_ih; zeros j>=50
//  bbv [256]      : b_ih + b_hh (col 4j+g)
//  hb  [8*2*768]  : per-warp double-buffered h, [warp][buf][unit*12 + 2s(+1) dup]
//  xs  [2*32*68]  : double-buffered x tiles, [tt][8*warp + 2q dup]
#define OFF_WS  0
#define OFF_BB  (51*G4)                 // 13056
#define OFF_HB  (OFF_BB + G4)           // 13312
#define OFF_XS  (OFF_HB + 8*2*HBW)      // 13312 + 12288 = 25600
#define SMEM_FLOATS (OFF_XS + 2*XBUF)   // 29952 floats = 119808 B

__global__ void __launch_bounds__(NTHREADS, 1) lstm_q_kernel(
    const float* __restrict__ x,    const float* __restrict__ W_ih,
    const float* __restrict__ W_hh, const float* __restrict__ b_ih,
    const float* __restrict__ b_hh, const float* __restrict__ Wp,
    const float* __restrict__ bp,   const float* __restrict__ qw,
    const float* __restrict__ Wo,   const float* __restrict__ bo,
    float* __restrict__ out)
{
    extern __shared__ float sm[];
    float* Ws  = sm + OFF_WS;
    float* bbv = sm + OFF_BB;
    float* hb  = sm + OFF_HB;
    float* xs  = sm + OFF_XS;

    const int tid   = threadIdx.x;
    const int lane  = tid & 31;
    const int warp  = tid >> 5;
    const int bbase = blockIdx.x * SAMPLES;
    float* hwarp = hb + warp * (2 * HBW);      // this warp's private h region

    // ---- stage weights into shared (whole block) ----
    for (int idx = tid; idx < 51 * G4; idx += NTHREADS) {
        int k = idx >> 8, c = idx & 255;
        int jj = c >> 2, g = c & 3;
        float v = 0.f;
        if (jj < HDIM) {
            if (k < HDIM)      v = W_hh[(g * HDIM + jj) * HDIM + k];
            else               v = W_ih[g * HDIM + jj];          // row 50
        }
        Ws[idx] = v;
    }
    for (int idx = tid; idx < G4; idx += NTHREADS) {
        int jj = idx >> 2, g = idx & 3;
        bbv[idx] = (jj < HDIM) ? (b_ih[g * HDIM + jj] + b_hh[g * HDIM + jj]) : 0.f;
    }
    for (int idx = tid; idx < 8 * 2 * HBW; idx += NTHREADS) hb[idx] = 0.f;
    // prefill x tile 0: coalesced read, duplicated transposed store
    for (int idx = tid; idx < 32 * 32; idx += NTHREADS) {
        int ss = idx >> 5, tt = idx & 31;
        float v = x[(bbase + ss) * TSTEPS + tt];
        *(ull*)(xs + tt * XROW + 8 * (ss >> 2) + 2 * (ss & 3)) = pack2(v, v);
    }
    __syncthreads();

    // persistent constants: bias + W_ih row as natural (if),(go) pairs
    ulonglong2 bb0 = *(const ulonglong2*)(bbv + 4 * lane);
    ulonglong2 bb1 = *(const ulonglong2*)(bbv + 4 * lane + 128);
    ulonglong2 xw0 = *(const ulonglong2*)(Ws + 50 * G4 + 4 * lane);
    ulonglong2 xw1 = *(const ulonglong2*)(Ws + 50 * G4 + 4 * lane + 128);

    float c0[4], c1[4];     // cell state: unit lane / unit lane+32, 4 samples
    #pragma unroll
    for (int s = 0; s < 4; s++) { c0[s] = 0.f; c1[s] = 0.f; }

    int buf = 0;

    for (int t = 0; t < TSTEPS; t++) {
        __syncwarp();       // prev-step h stores visible within warp

        // per-warp refill of next x tile (own 4 samples only)
        if ((t & 31) == 0 && t + 32 < TSTEPS) {
            float* xd = xs + (((t >> 5) & 1) ^ 1) * XBUF;
            #pragma unroll
            for (int q = 0; q < 4; q++) {
                float v = x[(bbase + 4 * warp + q) * TSTEPS + t + 32 + lane];
                *(ull*)(xd + lane * XROW + 8 * warp + 2 * q) = pack2(v, v);
            }
            __syncwarp();
        }

        const float* hrow = hwarp + buf * HBW;
        const float* xrow = xs + ((t >> 5) & 1) * XBUF + (t & 31) * XROW + 8 * warp;

        ull aif0[4], ago0[4], aif1[4], ago1[4];
        #pragma unroll
        for (int s = 0; s < 4; s++) {
            aif0[s] = bb0.x; ago0[s] = bb0.y;
            aif1[s] = bb1.x; ago1[s] = bb1.y;
        }

        #pragma unroll 10
        for (int k = 0; k < 50; k++) {
            ulonglong2 w0 = *(const ulonglong2*)(Ws + k * G4 + 4 * lane);        // dense
            ulonglong2 w1 = *(const ulonglong2*)(Ws + k * G4 + 4 * lane + 128);  // dense
            ulonglong2 hA = *(const ulonglong2*)(hrow + k * HW);       // (s0,s0),(s1,s1)
            ulonglong2 hB = *(const ulonglong2*)(hrow + k * HW + 4);   // (s2,s2),(s3,s3)
            ull hd[4] = { hA.x, hA.y, hB.x, hB.y };
            #pragma unroll
            for (int s = 0; s < 4; s++) {
                aif0[s] = fma2(hd[s], w0.x, aif0[s]);
                ago0[s] = fma2(hd[s], w0.y, ago0[s]);
                aif1[s] = fma2(hd[s], w1.x, aif1[s]);
                ago1[s] = fma2(hd[s], w1.y, ago1[s]);
            }
        }
        // x contribution (row 50, persistent registers)
        {
            ulonglong2 xA = *(const ulonglong2*)(xrow + 0);
            ulonglong2 xB = *(const ulonglong2*)(xrow + 4);
            ull xd[4] = { xA.x, xA.y, xB.x, xB.y };
            #pragma unroll
            for (int s = 0; s < 4; s++) {
                aif0[s] = fma2(xd[s], xw0.x, aif0[s]);
                ago0[s] = fma2(xd[s], xw0.y, ago0[s]);
                aif1[s] = fma2(xd[s], xw1.x, aif1[s]);
                ago1[s] = fma2(xd[s], xw1.y, ago1[s]);
            }
        }

        // ---- gates: unit group 0 (j = lane) ----
        float* hn = hwarp + (buf ^ 1) * HBW;
        {
            float hv[4];
            #pragma unroll
            for (int s = 0; s < 4; s++) {
                float zi, zf, zg, zo;
                unpack2(aif0[s], zi, zf);
                unpack2(ago0[s], zg, zo);
                float ig = sigmoidf_(zi);
                float fg = sigmoidf_(zf);
                float gg = tanhf_(zg);
                float og = sigmoidf_(zo);
                float c  = fmaf(fg, c0[s], ig * gg);
                c0[s] = c;
                hv[s] = og * tanhf_(c);
            }
            if (lane < HDIM) {   // always true (lane<32<50) — kept for symmetry
                ulonglong2 wA, wB;
                wA.x = pack2(hv[0], hv[0]); wA.y = pack2(hv[1], hv[1]);
                wB.x = pack2(hv[2], hv[2]); wB.y = pack2(hv[3], hv[3]);
                *(ulonglong2*)(hn + lane * HW)     = wA;
                *(ulonglong2*)(hn + lane * HW + 4) = wB;
            }
        }
        // ---- gates: unit group 1 (j = lane + 32) ----
        {
            float hv[4];
            #pragma unroll
            for (int s = 0; s < 4; s++) {
                float zi, zf, zg, zo;
                unpack2(aif1[s], zi, zf);
                unpack2(ago1[s], zg, zo);
                float ig = sigmoidf_(zi);
                float fg = sigmoidf_(zf);
                float gg = tanhf_(zg);
                float og = sigmoidf_(zo);
                float c  = fmaf(fg, c1[s], ig * gg);
                c1[s] = c;
                hv[s] = og * tanhf_(c);
            }
            if (lane + 32 < HDIM) {   // lanes 0..17 only
                ulonglong2 wA, wB;
                wA.x = pack2(hv[0], hv[0]); wA.y = pack2(hv[1], hv[1]);
                wB.x = pack2(hv[2], hv[2]); wB.y = pack2(hv[3], hv[3]);
                *(ulonglong2*)(hn + (lane + 32) * HW)     = wA;
                *(ulonglong2*)(hn + (lane + 32) * HW + 4) = wB;
            }
        }
        buf ^= 1;
    }

    __syncthreads();   // all warps' final h visible (final h in buf=0 region)

    // ---------------- quantum head: 1 thread per sample ----------------
    if (tid < SAMPLES) {
        const int w_own = tid >> 2, sl = tid & 3;
        const float* hfin = hb + w_own * (2 * HBW) + 2 * sl;   // buf 0; h(k) at k*HW

        float ang[4];
        #pragma unroll
        for (int w = 0; w < 4; w++) {
            float a = bp[w];
            for (int k = 0; k < HDIM; k++) a = fmaf(Wp[w * HDIM + k], hfin[k * HW], a);
            ang[w] = tanhf_(a) * 1.5707963267948966f;
        }

        float re[16], im[16];
        #pragma unroll
        for (int i = 0; i < 16; i++) { re[i] = 0.f; im[i] = 0.f; }
        re[0] = 1.f;

        // RX embedding (wire w <-> bit 3-w)
        #pragma unroll
        for (int w = 0; w < 4; w++) {
            float sw, cw;
            sincosf(0.5f * ang[w], &sw, &cw);
            const int m = 8 >> w;
            #pragma unroll
            for (int i0 = 0; i0 < 16; i0++) {
                if (!(i0 & m)) {
                    int i1 = i0 | m;
                    float r0 = re[i0], q0 = im[i0], r1 = re[i1], q1 = im[i1];
                    re[i0] = cw * r0 + sw * q1;  im[i0] = cw * q0 - sw * r1;
                    re[i1] = cw * r1 + sw * q0;  im[i1] = cw * q1 - sw * r0;
                }
            }
        }

        // StronglyEntanglingLayers
        #pragma unroll
        for (int l = 0; l < 2; l++) {
            #pragma unroll
            for (int w = 0; w < 4; w++) {
                const float* q = qw + (l * 4 + w) * 3;
                float phi = q[0], th = q[1], om = q[2];
                float st_, ct_; sincosf(0.5f * th, &st_, &ct_);
                float sa, ca;   sincosf(0.5f * (phi + om), &sa, &ca);
                float sb2, cb2; sincosf(0.5f * (phi - om), &sb2, &cb2);
                float u00r =  ct_ * ca,  u00i = -ct_ * sa;
                float u01r = -st_ * cb2, u01i = -st_ * sb2;
                float u10r =  st_ * cb2, u10i = -st_ * sb2;
                float u11r =  ct_ * ca,  u11i =  ct_ * sa;
                const int m = 8 >> w;
                #pragma unroll
                for (int i0 = 0; i0 < 16; i0++) {
                    if (!(i0 & m)) {
                        int i1 = i0 | m;
                        float r0 = re[i0], q0 = im[i0], r1 = re[i1], q1 = im[i1];
                        re[i0] = u00r*r0 - u00i*q0 + u01r*r1 - u01i*q1;
                        im[i0] = u00r*q0 + u00i*r0 + u01r*q1 + u01i*r1;
                        re[i1] = u10r*r0 - u10i*q0 + u11r*r1 - u11i*q1;
                        im[i1] = u10r*q0 + u10i*r0 + u11r*q1 + u11i*r1;
                    }
                }
            }
            const int r = (l % 3) + 1;
            #pragma unroll
            for (int w = 0; w < 4; w++) {
                const int cm = 8 >> w;
                const int tm = 8 >> ((w + r) & 3);
                #pragma unroll
                for (int i0 = 0; i0 < 16; i0++) {
                    if ((i0 & cm) && !(i0 & tm)) {
                        int i1 = i0 | tm;
                        float tr = re[i0]; re[i0] = re[i1]; re[i1] = tr;
                        float ti = im[i0]; im[i0] = im[i1]; im[i1] = ti;
                    }
                }
            }
        }

        float o = bo[0];
        #pragma unroll
        for (int w = 0; w < 4; w++) {
            const int m = 8 >> w;
            float ev = 0.f;
            #pragma unroll
            for (int i = 0; i < 16; i++) {
                float p = re[i] * re[i] + im[i] * im[i];
                ev += (i & m) ? -p : p;
            }
            o = fmaf(Wo[w], ev, o);
        }
        out[bbase + tid] = o;
    }
}

extern "C" void kernel_launch(void* const* d_in, const int* in_sizes, int n_in,
                              void* d_out, int out_size) {
    const float* x    = (const float*)d_in[0];
    const float* W_ih = (const float*)d_in[1];
    const float* W_hh = (const float*)d_in[2];
    const float* b_ih = (const float*)d_in[3];
    const float* b_hh = (const float*)d_in[4];
    const float* Wp   = (const float*)d_in[5];
    const float* bp   = (const float*)d_in[6];
    const float* qw   = (const float*)d_in[7];
    const float* Wo   = (const float*)d_in[8];
    const float* bo   = (const float*)d_in[9];
    float* out = (float*)d_out;

    const size_t smem = SMEM_FLOATS * sizeof(float);
    cudaFuncSetAttribute(lstm_q_kernel, cudaFuncAttributeMaxDynamicSharedMemorySize, (int)smem);

    lstm_q_kernel<<<4096 / SAMPLES, NTHREADS, smem>>>(
        x, W_ih, W_hh, b_ih, b_hh, Wp, bp, qw, Wo, bo, out);
}

// round 13
// speedup vs baseline: 1.4305x; 1.4305x over previous
#include <cuda_runtime.h>

#define NTHREADS 256
#define SAMPLES  32
#define HDIM     50
#define G4       256           // 64 units * 4 gates, cols 4j+g
#define TSTEPS   256
#define HROW     34            // floats per h row [k][s0..s31] + 2 pad
#define HBUF     (50*HROW)
#define XROW     34
#define XBUF     (32*XROW)

typedef unsigned long long ull;

__device__ __forceinline__ ull pack2(float lo, float hi) {
    ull r; asm("mov.b64 %0, {%1,%2};" : "=l"(r) : "f"(lo), "f"(hi)); return r;
}
__device__ __forceinline__ void unpack2(ull v, float& lo, float& hi) {
    asm("mov.b64 {%0,%1}, %2;" : "=f"(lo), "=f"(hi) : "l"(v));
}
__device__ __forceinline__ ull fma2(ull a, ull b, ull c) {
    ull d; asm("fma.rn.f32x2 %0, %1, %2, %3;" : "=l"(d) : "l"(a), "l"(b), "l"(c)); return d;
}
// HW tanh: 1 MUFU op (vs 2-op exp/rcp chain)
__device__ __forceinline__ float tanh_fast(float x) {
    float y; asm("tanh.approx.f32 %0, %1;" : "=f"(y) : "f"(x)); return y;
}
__device__ __forceinline__ float sigmoid_fast(float x) {
    return fmaf(0.5f, tanh_fast(0.5f * x), 0.5f);
}
// exact versions for the head
__device__ __forceinline__ float sigmoidf_(float x) {
    return __fdividef(1.f, 1.f + __expf(-x));
}
__device__ __forceinline__ float tanhf_(float x) {
    return fmaf(2.f, sigmoidf_(2.f * x), -1.f);
}
__device__ __forceinline__ void cohort_bar(int id) {
    asm volatile("bar.sync %0, %1;" :: "r"(id), "r"(128) : "memory");
}

// Dynamic shared layout (floats):
//  Ws  [51*256] : rows 0..49 = W_hh (col c=4j+g), row 50 = W_ih; zeros j>=50
//  bbv [256]    : b_ih + b_hh (col 4j+g)
//  hb  [2*50*34]: double-buffered hidden state, rows [k][s]
//  xs  [2*32*34]: double-buffered x tiles, rows [tt][s]
#define OFF_WS  0
#define OFF_BB  (51*G4)
#define OFF_HB  (OFF_BB + G4)
#define OFF_XS  (OFF_HB + 2*HBUF)
#define SMEM_FLOATS (OFF_XS + 2*XBUF)

__global__ void __launch_bounds__(NTHREADS, 1) lstm_q_kernel(
    const float* __restrict__ x,    const float* __restrict__ W_ih,
    const float* __restrict__ W_hh, const float* __restrict__ b_ih,
    const float* __restrict__ b_hh, const float* __restrict__ Wp,
    const float* __restrict__ bp,   const float* __restrict__ qw,
    const float* __restrict__ Wo,   const float* __restrict__ bo,
    float* __restrict__ out)
{
    extern __shared__ float sm[];
    float* Ws  = sm + OFF_WS;
    float* bbv = sm + OFF_BB;
    float* hb  = sm + OFF_HB;
    float* xs  = sm + OFF_XS;

    const int tid   = threadIdx.x;
    const int lane  = tid & 31;
    const int warp  = tid >> 5;
    const int coh   = warp >> 2;           // cohort 0: warps 0-3 / cohort 1: warps 4-7
    const int ctid  = tid & 127;           // thread id within cohort
    const int ug    = warp & 1;            // unit group (0..1)
    const int sg    = (warp >> 1) & 1;     // sample group within cohort (0..1)
    const int j     = 32 * ug + lane;      // this thread's hidden unit (0..63)
    const int sb    = 16 * coh + 8 * sg;   // first of 8 samples
    const int bbase = blockIdx.x * SAMPLES;
    const int bid   = coh + 1;             // named barrier id for this cohort

    // ---- stage weights into shared (whole block) ----
    for (int idx = tid; idx < 51 * G4; idx += NTHREADS) {
        int k = idx >> 8, c = idx & 255;
        int jj = c >> 2, g = c & 3;
        float v = 0.f;
        if (jj < HDIM) {
            if (k < HDIM)      v = W_hh[(g * HDIM + jj) * HDIM + k];
            else               v = W_ih[g * HDIM + jj];          // row 50
        }
        Ws[idx] = v;
    }
    for (int idx = tid; idx < G4; idx += NTHREADS) {
        int jj = idx >> 2, g = idx & 3;
        bbv[idx] = (jj < HDIM) ? (b_ih[g * HDIM + jj] + b_hh[g * HDIM + jj]) : 0.f;
    }
    for (int idx = tid; idx < 2 * HBUF; idx += NTHREADS) hb[idx] = 0.f;
    // prefill x tile 0 (buffer 0): coalesced read, transposed store
    for (int idx = tid; idx < 32 * 32; idx += NTHREADS) {
        int ss = idx >> 5, tt = idx & 31;
        xs[tt * XROW + ss] = x[(bbase + ss) * TSTEPS + tt];
    }
    __syncthreads();

    // persistent packed biases / W_ih for this thread's 4 gate columns
    float4 b4 = *(const float4*)(bbv + 4 * j);
    ull bbg[4] = { pack2(b4.x, b4.x), pack2(b4.y, b4.y),
                   pack2(b4.z, b4.z), pack2(b4.w, b4.w) };
    float4 xw4 = *(const float4*)(Ws + 50 * G4 + 4 * j);
    ull xwg[4] = { pack2(xw4.x, xw4.x), pack2(xw4.y, xw4.y),
                   pack2(xw4.z, xw4.z), pack2(xw4.w, xw4.w) };

    float c_st[8];
    #pragma unroll
    for (int i = 0; i < 8; i++) c_st[i] = 0.f;

    int buf = 0;

    for (int t = 0; t < TSTEPS; t++) {
        cohort_bar(bid);               // this cohort's prev-step h writes (+ x refill) visible

        // refill next x tile for THIS COHORT's 16 samples only
        if ((t & 31) == 0 && t + 32 < TSTEPS) {
            float* xd = xs + (((t >> 5) & 1) ^ 1) * XBUF;
            for (int idx = ctid; idx < 16 * 32; idx += 128) {
                int ss = 16 * coh + (idx >> 5), tt = idx & 31;
                xd[tt * XROW + ss] = x[(bbase + ss) * TSTEPS + t + 32 + tt];
            }
        }

        const float* hB   = hb + buf * HBUF;
        const float* xrow = xs + ((t >> 5) & 1) * XBUF + (t & 31) * XROW + sb;

        ull acc[4][4];                 // [gate][sample-pair]
        #pragma unroll
        for (int g = 0; g < 4; g++)
            #pragma unroll
            for (int p = 0; p < 4; p++) acc[g][p] = bbg[g];

        #pragma unroll 10
        for (int k = 0; k < 50; k++) {
            float4 w4 = *(const float4*)(Ws + k * G4 + 4 * j);   // dense LDS.128
            ull wg[4] = { pack2(w4.x, w4.x), pack2(w4.y, w4.y),
                          pack2(w4.z, w4.z), pack2(w4.w, w4.w) };
            const float* hr = hB + k * HROW + sb;
            ull hp[4];
            #pragma unroll
            for (int p = 0; p < 4; p++) hp[p] = *(const ull*)(hr + 2 * p); // bcast LDS.64
            #pragma unroll
            for (int g = 0; g < 4; g++)
                #pragma unroll
                for (int p = 0; p < 4; p++)
                    acc[g][p] = fma2(hp[p], wg[g], acc[g][p]);
        }
        // x contribution (row 50 weights persistent in registers)
        {
            ull xp[4];
            #pragma unroll
            for (int p = 0; p < 4; p++) xp[p] = *(const ull*)(xrow + 2 * p);
            #pragma unroll
            for (int g = 0; g < 4; g++)
                #pragma unroll
                for (int p = 0; p < 4; p++)
                    acc[g][p] = fma2(xp[p], xwg[g], acc[g][p]);
        }

        // ---- gates: this thread = unit j, samples sb..sb+7 (fast tanh path) ----
        float* hn = hb + (buf ^ 1) * HBUF + j * HROW + sb;
        #pragma unroll
        for (int p = 0; p < 4; p++) {
            float zi0, zi1, zf0, zf1, zg0, zg1, zo0, zo1;
            unpack2(acc[0][p], zi0, zi1);
            unpack2(acc[1][p], zf0, zf1);
            unpack2(acc[2][p], zg0, zg1);
            unpack2(acc[3][p], zo0, zo1);
            float i0 = sigmoid_fast(zi0), i1 = sigmoid_fast(zi1);
            float f0 = sigmoid_fast(zf0), f1 = sigmoid_fast(zf1);
            float g0 = tanh_fast(zg0),    g1 = tanh_fast(zg1);
            float o0 = sigmoid_fast(zo0), o1 = sigmoid_fast(zo1);
            float c0 = fmaf(f0, c_st[2*p],   i0 * g0);
            float c1 = fmaf(f1, c_st[2*p+1], i1 * g1);
            c_st[2*p]   = c0;
            c_st[2*p+1] = c1;
            float h0 = o0 * tanh_fast(c0);
            float h1 = o1 * tanh_fast(c1);
            if (j < HDIM) *(ull*)(hn + 2 * p) = pack2(h0, h1);
        }
        buf ^= 1;
    }

    __syncthreads();   // both cohorts' final h visible

    // ---------------- quantum head: 1 thread per sample (exact math) ----------------
    if (tid < SAMPLES) {
        const float* hfin = hb + buf * HBUF + tid;   // h[k][tid] at stride HROW

        float ang[4];
        #pragma unroll
        for (int w = 0; w < 4; w++) {
            float a = bp[w];
            for (int k = 0; k < HDIM; k++) a = fmaf(Wp[w * HDIM + k], hfin[k * HROW], a);
            ang[w] = tanhf_(a) * 1.5707963267948966f;
        }

        float re[16], im[16];
        #pragma unroll
        for (int i = 0; i < 16; i++) { re[i] = 0.f; im[i] = 0.f; }
        re[0] = 1.f;

        // RX embedding (wire w <-> bit 3-w)
        #pragma unroll
        for (int w = 0; w < 4; w++) {
            float sw, cw;
            sincosf(0.5f * ang[w], &sw, &cw);
            const int m = 8 >> w;
            #pragma unroll
            for (int i0 = 0; i0 < 16; i0++) {
                if (!(i0 & m)) {
                    int i1 = i0 | m;
                    float r0 = re[i0], q0 = im[i0], r1 = re[i1], q1 = im[i1];
                    re[i0] = cw * r0 + sw * q1;  im[i0] = cw * q0 - sw * r1;
                    re[i1] = cw * r1 + sw * q0;  im[i1] = cw * q1 - sw * r0;
                }
            }
        }

        // StronglyEntanglingLayers
        #pragma unroll
        for (int l = 0; l < 2; l++) {
            #pragma unroll
            for (int w = 0; w < 4; w++) {
                const float* q = qw + (l * 4 + w) * 3;
                float phi = q[0], th = q[1], om = q[2];
                float st_, ct_; sincosf(0.5f * th, &st_, &ct_);
                float sa, ca;   sincosf(0.5f * (phi + om), &sa, &ca);
                float sb2, cb2; sincosf(0.5f * (phi - om), &sb2, &cb2);
                float u00r =  ct_ * ca,  u00i = -ct_ * sa;
                float u01r = -st_ * cb2, u01i = -st_ * sb2;
                float u10r =  st_ * cb2, u10i = -st_ * sb2;
                float u11r =  ct_ * ca,  u11i =  ct_ * sa;
                const int m = 8 >> w;
                #pragma unroll
                for (int i0 = 0; i0 < 16; i0++) {
                    if (!(i0 & m)) {
                        int i1 = i0 | m;
                        float r0 = re[i0], q0 = im[i0], r1 = re[i1], q1 = im[i1];
                        re[i0] = u00r*r0 - u00i*q0 + u01r*r1 - u01i*q1;
                        im[i0] = u00r*q0 + u00i*r0 + u01r*q1 + u01i*r1;
                        re[i1] = u10r*r0 - u10i*q0 + u11r*r1 - u11i*q1;
                        im[i1] = u10r*q0 + u10i*r0 + u11r*q1 + u11i*r1;
                    }
                }
            }
            const int r = (l % 3) + 1;
            #pragma unroll
            for (int w = 0; w < 4; w++) {
                const int cm = 8 >> w;
                const int tm = 8 >> ((w + r) & 3);
                #pragma unroll
                for (int i0 = 0; i0 < 16; i0++) {
                    if ((i0 & cm) && !(i0 & tm)) {
                        int i1 = i0 | tm;
                        float tr = re[i0]; re[i0] = re[i1]; re[i1] = tr;
                        float ti = im[i0]; im[i0] = im[i1]; im[i1] = ti;
                    }
                }
            }
        }

        float o = bo[0];
        #pragma unroll
        for (int w = 0; w < 4; w++) {
            const int m = 8 >> w;
            float ev = 0.f;
            #pragma unroll
            for (int i = 0; i < 16; i++) {
                float p = re[i] * re[i] + im[i] * im[i];
                ev += (i & m) ? -p : p;
            }
            o = fmaf(Wo[w], ev, o);
        }
        out[bbase + tid] = o;
    }
}

extern "C" void kernel_launch(void* const* d_in, const int* in_sizes, int n_in,
                              void* d_out, int out_size) {
    const float* x    = (const float*)d_in[0];
    const float* W_ih = (const float*)d_in[1];
    const float* W_hh = (const float*)d_in[2];
    const float* b_ih = (const float*)d_in[3];
    const float* b_hh = (const float*)d_in[4];
    const float* Wp   = (const float*)d_in[5];
    const float* bp   = (const float*)d_in[6];
    const float* qw   = (const float*)d_in[7];
    const float* Wo   = (const float*)d_in[8];
    const float* bo   = (const float*)d_in[9];
    float* out = (float*)d_out;

    const size_t smem = SMEM_FLOATS * sizeof(float);
    cudaFuncSetAttribute(lstm_q_kernel, cudaFuncAttributeMaxDynamicSharedMemorySize, (int)smem);

    lstm_q_kernel<<<4096 / SAMPLES, NTHREADS, smem>>>(
        x, W_ih, W_hh, b_ih, b_hh, Wp, bp, qw, Wo, bo, out);
}

// round 14
// speedup vs baseline: 1.4674x; 1.0258x over previous
#include <cuda_runtime.h>

#define NTHREADS 256
#define SAMPLES  32
#define HDIM     50
#define G4       256           // 64 units * 4 gates, cols 4j+g
#define TSTEPS   256
#define HROW     36            // floats per h row [k][s0..s31] + 4 pad (16B-aligned rows)
#define HBUF     (50*HROW)
#define XROW     36
#define XBUF     (32*XROW)

typedef unsigned long long ull;

__device__ __forceinline__ ull pack2(float lo, float hi) {
    ull r; asm("mov.b64 %0, {%1,%2};" : "=l"(r) : "f"(lo), "f"(hi)); return r;
}
__device__ __forceinline__ void unpack2(ull v, float& lo, float& hi) {
    asm("mov.b64 {%0,%1}, %2;" : "=f"(lo), "=f"(hi) : "l"(v));
}
__device__ __forceinline__ ull fma2(ull a, ull b, ull c) {
    ull d; asm("fma.rn.f32x2 %0, %1, %2, %3;" : "=l"(d) : "l"(a), "l"(b), "l"(c)); return d;
}
// HW tanh: 1 MUFU op
__device__ __forceinline__ float tanh_fast(float x) {
    float y; asm("tanh.approx.f32 %0, %1;" : "=f"(y) : "f"(x)); return y;
}
__device__ __forceinline__ float sigmoid_fast(float x) {
    return fmaf(0.5f, tanh_fast(0.5f * x), 0.5f);
}
// exact versions for the head
__device__ __forceinline__ float sigmoidf_(float x) {
    return __fdividef(1.f, 1.f + __expf(-x));
}
__device__ __forceinline__ float tanhf_(float x) {
    return fmaf(2.f, sigmoidf_(2.f * x), -1.f);
}
__device__ __forceinline__ void cohort_bar(int id) {
    asm volatile("bar.sync %0, %1;" :: "r"(id), "r"(128) : "memory");
}

// Dynamic shared layout (floats):
//  Ws  [51*256] : rows 0..49 = W_hh (col c=4j+g), row 50 = W_ih; zeros j>=50
//  bbv [256]    : b_ih + b_hh (col 4j+g)
//  hb  [2*50*36]: double-buffered hidden state, rows [k][s]
//  xs  [2*32*36]: double-buffered x tiles, rows [tt][s]
//  pad [32]     : dead sink for stagger chain
#define OFF_WS  0
#define OFF_BB  (51*G4)
#define OFF_HB  (OFF_BB + G4)
#define OFF_XS  (OFF_HB + 2*HBUF)
#define OFF_PAD (OFF_XS + 2*XBUF)
#define SMEM_FLOATS (OFF_PAD + 32)

__global__ void __launch_bounds__(NTHREADS, 1) lstm_q_kernel(
    const float* __restrict__ x,    const float* __restrict__ W_ih,
    const float* __restrict__ W_hh, const float* __restrict__ b_ih,
    const float* __restrict__ b_hh, const float* __restrict__ Wp,
    const float* __restrict__ bp,   const float* __restrict__ qw,
    const float* __restrict__ Wo,   const float* __restrict__ bo,
    float* __restrict__ out)
{
    extern __shared__ float sm[];
    float* Ws  = sm + OFF_WS;
    float* bbv = sm + OFF_BB;
    float* hb  = sm + OFF_HB;
    float* xs  = sm + OFF_XS;

    const int tid   = threadIdx.x;
    const int lane  = tid & 31;
    const int warp  = tid >> 5;
    const int coh   = warp >> 2;           // cohort 0: warps 0-3 / cohort 1: warps 4-7
    const int ctid  = tid & 127;           // thread id within cohort
    const int ug    = warp & 1;            // unit group (0..1)
    const int sg    = (warp >> 1) & 1;     // sample group within cohort (0..1)
    const int j     = 32 * ug + lane;      // this thread's hidden unit (0..63)
    const int sb    = 16 * coh + 8 * sg;   // first of 8 samples
    const int bbase = blockIdx.x * SAMPLES;
    const int bid   = coh + 1;             // named barrier id for this cohort

    // ---- stage weights into shared (whole block) ----
    for (int idx = tid; idx < 51 * G4; idx += NTHREADS) {
        int k = idx >> 8, c = idx & 255;
        int jj = c >> 2, g = c & 3;
        float v = 0.f;
        if (jj < HDIM) {
            if (k < HDIM)      v = W_hh[(g * HDIM + jj) * HDIM + k];
            else               v = W_ih[g * HDIM + jj];          // row 50
        }
        Ws[idx] = v;
    }
    for (int idx = tid; idx < G4; idx += NTHREADS) {
        int jj = idx >> 2, g = idx & 3;
        bbv[idx] = (jj < HDIM) ? (b_ih[g * HDIM + jj] + b_hh[g * HDIM + jj]) : 0.f;
    }
    for (int idx = tid; idx < 2 * HBUF; idx += NTHREADS) hb[idx] = 0.f;
    // prefill x tile 0 (buffer 0): coalesced read, transposed store
    for (int idx = tid; idx < 32 * 32; idx += NTHREADS) {
        int ss = idx >> 5, tt = idx & 31;
        xs[tt * XROW + ss] = x[(bbase + ss) * TSTEPS + tt];
    }
    __syncthreads();

    // ---- anti-phase stagger: cohort 1 starts ~half a step late so its
    // FMA mainloop overlaps cohort 0's MUFU epilogue on every SMSP ----
    if (coh == 1) {
        float z = 0.f;
        #pragma unroll 1
        for (int i = 0; i < 600; i++)
            asm volatile("add.f32 %0, %0, 0f3F800000;" : "+f"(z));
        if (z < 0.f) sm[OFF_PAD + lane] = z;   // opaque sink, never taken
    }

    // persistent packed biases / W_ih for this thread's 4 gate columns
    float4 b4 = *(const float4*)(bbv + 4 * j);
    ull bbg[4] = { pack2(b4.x, b4.x), pack2(b4.y, b4.y),
                   pack2(b4.z, b4.z), pack2(b4.w, b4.w) };
    float4 xw4 = *(const float4*)(Ws + 50 * G4 + 4 * j);
    ull xwg[4] = { pack2(xw4.x, xw4.x), pack2(xw4.y, xw4.y),
                   pack2(xw4.z, xw4.z), pack2(xw4.w, xw4.w) };

    float c_st[8];
    #pragma unroll
    for (int i = 0; i < 8; i++) c_st[i] = 0.f;

    int buf = 0;

    for (int t = 0; t < TSTEPS; t++) {
        cohort_bar(bid);               // this cohort's prev-step h writes (+ x refill) visible

        // refill next x tile for THIS COHORT's 16 samples only
        if ((t & 31) == 0 && t + 32 < TSTEPS) {
            float* xd = xs + (((t >> 5) & 1) ^ 1) * XBUF;
            for (int idx = ctid; idx < 16 * 32; idx += 128) {
                int ss = 16 * coh + (idx >> 5), tt = idx & 31;
                xd[tt * XROW + ss] = x[(bbase + ss) * TSTEPS + t + 32 + tt];
            }
        }

        const float* hB   = hb + buf * HBUF;
        const float* xrow = xs + ((t >> 5) & 1) * XBUF + (t & 31) * XROW + sb;

        ull acc[4][4];                 // [gate][sample-pair]
        #pragma unroll
        for (int g = 0; g < 4; g++)
            #pragma unroll
            for (int p = 0; p < 4; p++) acc[g][p] = bbg[g];

        #pragma unroll 10
        for (int k = 0; k < 50; k++) {
            float4 w4 = *(const float4*)(Ws + k * G4 + 4 * j);   // dense LDS.128
            ull wg[4] = { pack2(w4.x, w4.x), pack2(w4.y, w4.y),
                          pack2(w4.z, w4.z), pack2(w4.w, w4.w) };
            const float* hr = hB + k * HROW + sb;                // 16B aligned
            ulonglong2 hq0 = *(const ulonglong2*)(hr);           // (h0,h1),(h2,h3)
            ulonglong2 hq1 = *(const ulonglong2*)(hr + 4);       // (h4,h5),(h6,h7)
            ull hp[4] = { hq0.x, hq0.y, hq1.x, hq1.y };
            #pragma unroll
            for (int g = 0; g < 4; g++)
                #pragma unroll
                for (int p = 0; p < 4; p++)
                    acc[g][p] = fma2(hp[p], wg[g], acc[g][p]);
        }
        // x contribution (row 50 weights persistent in registers)
        {
            ulonglong2 xq0 = *(const ulonglong2*)(xrow);
            ulonglong2 xq1 = *(const ulonglong2*)(xrow + 4);
            ull xp[4] = { xq0.x, xq0.y, xq1.x, xq1.y };
            #pragma unroll
            for (int g = 0; g < 4; g++)
                #pragma unroll
                for (int p = 0; p < 4; p++)
                    acc[g][p] = fma2(xp[p], xwg[g], acc[g][p]);
        }

        // ---- gates: this thread = unit j, samples sb..sb+7 (fast tanh path) ----
        float* hn = hb + (buf ^ 1) * HBUF + j * HROW + sb;
        float hv[8];
        #pragma unroll
        for (int p = 0; p < 4; p++) {
            float zi0, zi1, zf0, zf1, zg0, zg1, zo0, zo1;
            unpack2(acc[0][p], zi0, zi1);
            unpack2(acc[1][p], zf0, zf1);
            unpack2(acc[2][p], zg0, zg1);
            unpack2(acc[3][p], zo0, zo1);
            float i0 = sigmoid_fast(zi0), i1 = sigmoid_fast(zi1);
            float f0 = sigmoid_fast(zf0), f1 = sigmoid_fast(zf1);
            float g0 = tanh_fast(zg0),    g1 = tanh_fast(zg1);
            float o0 = sigmoid_fast(zo0), o1 = sigmoid_fast(zo1);
            float c0 = fmaf(f0, c_st[2*p],   i0 * g0);
            float c1 = fmaf(f1, c_st[2*p+1], i1 * g1);
            c_st[2*p]   = c0;
            c_st[2*p+1] = c1;
            hv[2*p]   = o0 * tanh_fast(c0);
            hv[2*p+1] = o1 * tanh_fast(c1);
        }
        if (j < HDIM) {
            *(float4*)(hn)     = make_float4(hv[0], hv[1], hv[2], hv[3]);  // STS.128
            *(float4*)(hn + 4) = make_float4(hv[4], hv[5], hv[6], hv[7]);  // conflict-free
        }
        buf ^= 1;
    }

    __syncthreads();   // both cohorts' final h visible

    // ---------------- quantum head: 1 thread per sample (exact math) ----------------
    if (tid < SAMPLES) {
        const float* hfin = hb + buf * HBUF + tid;   // h[k][tid] at stride HROW

        float ang[4];
        #pragma unroll
        for (int w = 0; w < 4; w++) {
            float a = bp[w];
            for (int k = 0; k < HDIM; k++) a = fmaf(Wp[w * HDIM + k], hfin[k * HROW], a);
            ang[w] = tanhf_(a) * 1.5707963267948966f;
        }

        float re[16], im[16];
        #pragma unroll
        for (int i = 0; i < 16; i++) { re[i] = 0.f; im[i] = 0.f; }
        re[0] = 1.f;

        // RX embedding (wire w <-> bit 3-w)
        #pragma unroll
        for (int w = 0; w < 4; w++) {
            float sw, cw;
            sincosf(0.5f * ang[w], &sw, &cw);
            const int m = 8 >> w;
            #pragma unroll
            for (int i0 = 0; i0 < 16; i0++) {
                if (!(i0 & m)) {
                    int i1 = i0 | m;
                    float r0 = re[i0], q0 = im[i0], r1 = re[i1], q1 = im[i1];
                    re[i0] = cw * r0 + sw * q1;  im[i0] = cw * q0 - sw * r1;
                    re[i1] = cw * r1 + sw * q0;  im[i1] = cw * q1 - sw * r0;
                }
            }
        }

        // StronglyEntanglingLayers
        #pragma unroll
        for (int l = 0; l < 2; l++) {
            #pragma unroll
            for (int w = 0; w < 4; w++) {
                const float* q = qw + (l * 4 + w) * 3;
                float phi = q[0], th = q[1], om = q[2];
                float st_, ct_; sincosf(0.5f * th, &st_, &ct_);
                float sa, ca;   sincosf(0.5f * (phi + om), &sa, &ca);
                float sb2, cb2; sincosf(0.5f * (phi - om), &sb2, &cb2);
                float u00r =  ct_ * ca,  u00i = -ct_ * sa;
                float u01r = -st_ * cb2, u01i = -st_ * sb2;
                float u10r =  st_ * cb2, u10i = -st_ * sb2;
                float u11r =  ct_ * ca,  u11i =  ct_ * sa;
                const int m = 8 >> w;
                #pragma unroll
                for (int i0 = 0; i0 < 16; i0++) {
                    if (!(i0 & m)) {
                        int i1 = i0 | m;
                        float r0 = re[i0], q0 = im[i0], r1 = re[i1], q1 = im[i1];
                        re[i0] = u00r*r0 - u00i*q0 + u01r*r1 - u01i*q1;
                        im[i0] = u00r*q0 + u00i*r0 + u01r*q1 + u01i*r1;
                        re[i1] = u10r*r0 - u10i*q0 + u11r*r1 - u11i*q1;
                        im[i1] = u10r*q0 + u10i*r0 + u11r*q1 + u11i*r1;
                    }
                }
            }
            const int r = (l % 3) + 1;
            #pragma unroll
            for (int w = 0; w < 4; w++) {
                const int cm = 8 >> w;
                const int tm = 8 >> ((w + r) & 3);
                #pragma unroll
                for (int i0 = 0; i0 < 16; i0++) {
                    if ((i0 & cm) && !(i0 & tm)) {
                        int i1 = i0 | tm;
                        float tr = re[i0]; re[i0] = re[i1]; re[i1] = tr;
                        float ti = im[i0]; im[i0] = im[i1]; im[i1] = ti;
                    }
                }
            }
        }

        float o = bo[0];
        #pragma unroll
        for (int w = 0; w < 4; w++) {
            const int m = 8 >> w;
            float ev = 0.f;
            #pragma unroll
            for (int i = 0; i < 16; i++) {
                float p = re[i] * re[i] + im[i] * im[i];
                ev += (i & m) ? -p : p;
            }
            o = fmaf(Wo[w], ev, o);
        }
        out[bbase + tid] = o;
    }
}

extern "C" void kernel_launch(void* const* d_in, const int* in_sizes, int n_in,
                              void* d_out, int out_size) {
    const float* x    = (const float*)d_in[0];
    const float* W_ih = (const float*)d_in[1];
    const float* W_hh = (const float*)d_in[2];
    const float* b_ih = (const float*)d_in[3];
    const float* b_hh = (const float*)d_in[4];
    const float* Wp   = (const float*)d_in[5];
    const float* bp   = (const float*)d_in[6];
    const float* qw   = (const float*)d_in[7];
    const float* Wo   = (const float*)d_in[8];
    const float* bo   = (const float*)d_in[9];
    float* out = (float*)d_out;

    const size_t smem = SMEM_FLOATS * sizeof(float);
    cudaFuncSetAttribute(lstm_q_kernel, cudaFuncAttributeMaxDynamicSharedMemorySize, (int)smem);

    lstm_q_kernel<<<4096 / SAMPLES, NTHREADS, smem>>>(
        x, W_ih, W_hh, b_ih, b_hh, Wp, bp, qw, Wo, bo, out);
}